// round 16
// baseline (speedup 1.0000x reference)
#include <cuda_runtime.h>

// db4 wavedec level-4 (mode='symmetric'), persistent CTAs (444 = 3/SM x 148).
// R15: phase-count reduction 9 -> 5 barriers per row:
//  - A's symmetric halo filled straight from GMEM during cp.async prefetch
//  - intermediate-buffer halos filled in-warp (writer warp == consumer warp,
//    __syncwarp only) inside dwt_level -> no dedicated ext phases
//  - cD1 copy-out + next-row prefetch merged into the L2 compute phase
//  - cD2/cD3 written direct to GMEM (small scatter), cD1 staged+vectorized
//
// Output row layout (8218 f32): [cA4:518 | cD4:518 | cD3:1030 | cD2:2053 | cD1:4099]

#define L0    8192
#define O1    4099
#define O2    2053
#define O3    1030
#define O4    518
#define TOT   8218

#define NROWS 2048
#define NT    256
#define GRID  444     // 148 SMs x 3 CTAs

// SMEM buffers (floats): [8-float left ext | body | 7-float right ext], even caps.
// Max read pair index is n_out+3 -> max ext float idx 2*n_out+7 (tail-masked).
#define CAP_A 8208    // 8+8192+7 = 8207
#define CAP_B 4116    // 8+4099+7 = 4114
#define CAP_C 2068    // 8+2053+7 = 2068
#define CAP_S 4102    // cD1 staged at S+1 (pairs at S+2, 8B aligned)
#define SMEM_FLOATS (CAP_A + CAP_B + CAP_C + CAP_S)   // 18494
#define SMEM_BYTES  (SMEM_FLOATS * 4)                 // 73976 -> 3 CTAs/SM

// pywt db4 rec_lo
#define R0  0.23037781330885523f
#define R1  0.7148465705525415f
#define R2  0.6308807679295904f
#define R3 (-0.02798376941698385f)
#define R4 (-0.18703481171888114f)
#define R5  0.030841381835986965f
#define R6  0.032883011666982945f
#define R7 (-0.010597401784997278f)

typedef unsigned long long u64;

static __device__ __forceinline__ u64 pack2(float lo, float hi) {
    u64 r; asm("mov.b64 %0, {%1, %2};" : "=l"(r) : "f"(lo), "f"(hi)); return r;
}
static __device__ __forceinline__ u64 mul2(u64 a, u64 b) {
    u64 d; asm("mul.rn.f32x2 %0, %1, %2;" : "=l"(d) : "l"(a), "l"(b)); return d;
}
static __device__ __forceinline__ u64 fma2(u64 a, u64 b, u64 c) {
    u64 d; asm("fma.rn.f32x2 %0, %1, %2, %3;" : "=l"(d) : "l"(a), "l"(b), "l"(c)); return d;
}
static __device__ __forceinline__ float hadd2(u64 v) {
    float x, y; asm("mov.b64 {%0, %1}, %2;" : "=f"(x), "=f"(y) : "l"(v)); return x + y;
}

static __device__ __forceinline__ void cp16(float* smem_dst, const float* gmem_src) {
    unsigned s = (unsigned)__cvta_generic_to_shared(smem_dst);
    asm volatile("cp.async.cg.shared.global [%0], [%1], 16;" :: "r"(s), "l"(gmem_src));
}
static __device__ __forceinline__ void cp_commit() { asm volatile("cp.async.commit_group;"); }
static __device__ __forceinline__ void cp_wait0()  { asm volatile("cp.async.wait_group 0;"); }

struct Coef {
    u64 cl0, cl1, cl2, cl3;   // lo: (R0,R1)(R2,R3)(R4,R5)(R6,R7)
    u64 ch0, ch1, ch2, ch3;   // hi: H_t = (-1)^t R_{7-t}
};
static __device__ __forceinline__ Coef make_coef() {
    Coef c;
    c.cl0 = pack2(R0, R1);  c.cl1 = pack2(R2, R3);
    c.cl2 = pack2(R4, R5);  c.cl3 = pack2(R6, R7);
    c.ch0 = pack2(R7, -R6); c.ch1 = pack2(R5, -R4);
    c.ch2 = pack2(R3, -R2); c.ch3 = pack2(R1, -R0);
    return c;
}

// Prefetch a row into A (cp.async) and fill A's halo straight from GMEM.
static __device__ __forceinline__ void prefetch_row(float* Aext, const float* xr) {
    #pragma unroll
    for (int k = 0; k < L0 / 4 / NT; k++) {
        int i = threadIdx.x + k * NT;
        cp16(Aext + 8 + 4 * i, xr + 4 * i);
    }
    cp_commit();
    int t = threadIdx.x;
    if (t < 6) {
        Aext[2 + t] = xr[5 - t];                      // in[-6..-1] = x[5..0]
    } else if (t < 13) {
        int m = t - 6;
        Aext[8 + L0 + m] = xr[L0 - 1 - m];            // in[n..n+6] = x[n-1..n-7]
    }
}

// One DWT level. p_k = (ext[2k], ext[2k+1]); output i uses p_{i+1}..p_{i+4}.
// Thread t owns outputs [t*T, t*T+T) in chunks of <=CH with batched preloads.
// RTHR >= 0: fill this buffer's halo in-warp (left: threads 0..5 / warp 0;
// right: threads RTHR..RTHR+6, same warp as all right-halo consumers).
#define CH 9
template<int T, int RTHR>
static __device__ __forceinline__ void dwt_level(
    float* __restrict__ ext, int n, int n_out,
    float* __restrict__ outA, float* __restrict__ outD)
{
    if (RTHR >= 0) {
        int t = threadIdx.x;
        if (t < 6) ext[2 + t] = ext[8 + 5 - t];                       // left halo
        if ((unsigned)(t - RTHR) < 7u) {
            int m = t - RTHR;
            ext[8 + n + m] = ext[8 + n - 1 - m];                      // right halo
        }
        __syncwarp();
    }
    const int i0 = threadIdx.x * T;
    if (i0 >= n_out) return;
    const int rem = n_out - i0;
    const int lim = rem < T ? rem : T;

    const Coef c = make_coef();
    const u64* pp = reinterpret_cast<const u64*>(ext) + (i0 + 1);

    #pragma unroll
    for (int base = 0; base < T; base += CH) {
        if (base < lim) {
            const int Bn = (lim - base < CH) ? (lim - base) : CH;
            u64 p[CH + 3];
            #pragma unroll
            for (int k = 0; k < CH + 3; k++)
                if (k < Bn + 3) p[k] = pp[base + k];
            #pragma unroll
            for (int j = 0; j < CH; j++) {
                if (j < T - base && j < Bn) {
                    u64 al = mul2(c.cl0, p[j]);
                    al = fma2(c.cl1, p[j + 1], al);
                    al = fma2(c.cl2, p[j + 2], al);
                    al = fma2(c.cl3, p[j + 3], al);
                    u64 ah = mul2(c.ch0, p[j]);
                    ah = fma2(c.ch1, p[j + 1], ah);
                    ah = fma2(c.ch2, p[j + 2], ah);
                    ah = fma2(c.ch3, p[j + 3], ah);
                    outA[i0 + base + j] = hadd2(al);
                    outD[i0 + base + j] = hadd2(ah);
                }
            }
        }
    }
}

__global__ void __launch_bounds__(NT, 3)
wavedec_db4_l4_kernel(const float* __restrict__ x, float* __restrict__ out)
{
    extern __shared__ float sm[];
    float* A = sm;                          // row (ext)
    float* B = A + CAP_A;                   // cA1, later cA3 (ext)
    float* C = B + CAP_B;                   // cA2 (ext)
    float* S = C + CAP_C;                   // cD1 staging (at S+1)

    prefetch_row(A, x + (size_t)blockIdx.x * L0);

    for (int r = blockIdx.x; r < NROWS; r += GRID) {
        float* orow = out + (size_t)r * TOT;

        cp_wait0();
        __syncthreads();                                  // P1: A ready (incl halo)

        // P2 — Level 1: 8192 -> 4099. cA1 -> B, cD1 -> S+1.
        dwt_level<17, -1>(A, L0, O1, B + 8, S + 1);
        __syncthreads();

        // P3 — prefetch next row | copy cD1 out (vectorized) | Level 2.
        {
            int rn = r + GRID;
            if (rn < NROWS) prefetch_row(A, x + (size_t)rn * L0);
        }
        {
            if (threadIdx.x == 0) orow[4119] = S[1];      // odd head element
            const u64* sp = reinterpret_cast<const u64*>(S + 2);
            u64* gp = reinterpret_cast<u64*>(orow + 4120);
            #pragma unroll 4
            for (int p = threadIdx.x; p < (O1 - 1) / 2; p += NT) gp[p] = sp[p];
        }
        // Level 2: 4099 -> 2053. cA2 -> C, cD2 direct. Right-halo warp: 224..230.
        dwt_level<9, 224>(B, O1, O2, C + 8, orow + (O4 + O4 + O3));
        __syncthreads();

        // P4 — Level 3: 2053 -> 1030. cA3 -> B, cD3 direct. Halo warp 192..198.
        dwt_level<5, 192>(C, O2, O3, B + 8, orow + (O4 + O4));
        __syncthreads();

        // P5 — Level 4: 1030 -> 518, straight to GMEM. Halo warp 160..166.
        dwt_level<3, 160>(B, O3, O4, orow, orow + O4);
        __syncthreads();
    }
}

extern "C" void kernel_launch(void* const* d_in, const int* in_sizes, int n_in,
                              void* d_out, int out_size)
{
    (void)in_sizes; (void)n_in; (void)out_size;
    const float* x = (const float*)d_in[0];
    float* out = (float*)d_out;

    cudaFuncSetAttribute(wavedec_db4_l4_kernel,
                         cudaFuncAttributeMaxDynamicSharedMemorySize, SMEM_BYTES);
    wavedec_db4_l4_kernel<<<GRID, NT, SMEM_BYTES>>>(x, out);
}

// round 17
// speedup vs baseline: 1.0623x; 1.0623x over previous
#include <cuda_runtime.h>

// db4 wavedec level-4 (mode='symmetric'), persistent CTAs (444 = 3/SM x 148).
// R17 = R14's coalesced staged stores + R15's phase reduction (6 barriers/row):
//  - A's halo filled straight from GMEM during cp.async prefetch
//  - B/C halos filled in-warp (writer warp == consumer warp, __syncwarp)
//  - cD1 staged in S[1..], copied out (u64) during the prefetch phase
//  - cD2 staged in S[0..2052], copied out during the L3 phase (disjoint halves)
//  - cD3 staged in S[2054..], copied out during the L4 phase
//  - only L4's 2x518 outputs go direct (tiny scatter)
//
// Output row layout (8218 f32): [cA4:518 | cD4:518 | cD3:1030 | cD2:2053 | cD1:4099]

#define L0    8192
#define O1    4099
#define O2    2053
#define O3    1030
#define O4    518
#define TOT   8218

#define NROWS 2048
#define NT    256
#define GRID  444     // 148 SMs x 3 CTAs

// SMEM buffers (floats): [8-float left ext | body | 7-float right ext]
#define CAP_A 8208    // 8+8192+7
#define CAP_B 4116    // 8+4099+7
#define CAP_C 2068    // 8+2053+7
#define CAP_S 4102    // cD1 at S+1; later cD2 at S+0, cD3 at S+2054
#define SMEM_FLOATS (CAP_A + CAP_B + CAP_C + CAP_S)   // 18494
#define SMEM_BYTES  (SMEM_FLOATS * 4)                 // 73976 -> 3 CTAs/SM

// pywt db4 rec_lo
#define R0  0.23037781330885523f
#define R1  0.7148465705525415f
#define R2  0.6308807679295904f
#define R3 (-0.02798376941698385f)
#define R4 (-0.18703481171888114f)
#define R5  0.030841381835986965f
#define R6  0.032883011666982945f
#define R7 (-0.010597401784997278f)

typedef unsigned long long u64;

static __device__ __forceinline__ u64 pack2(float lo, float hi) {
    u64 r; asm("mov.b64 %0, {%1, %2};" : "=l"(r) : "f"(lo), "f"(hi)); return r;
}
static __device__ __forceinline__ u64 mul2(u64 a, u64 b) {
    u64 d; asm("mul.rn.f32x2 %0, %1, %2;" : "=l"(d) : "l"(a), "l"(b)); return d;
}
static __device__ __forceinline__ u64 fma2(u64 a, u64 b, u64 c) {
    u64 d; asm("fma.rn.f32x2 %0, %1, %2, %3;" : "=l"(d) : "l"(a), "l"(b), "l"(c)); return d;
}
static __device__ __forceinline__ float hadd2(u64 v) {
    float x, y; asm("mov.b64 {%0, %1}, %2;" : "=f"(x), "=f"(y) : "l"(v)); return x + y;
}

static __device__ __forceinline__ void cp16(float* smem_dst, const float* gmem_src) {
    unsigned s = (unsigned)__cvta_generic_to_shared(smem_dst);
    asm volatile("cp.async.cg.shared.global [%0], [%1], 16;" :: "r"(s), "l"(gmem_src));
}
static __device__ __forceinline__ void cp_commit() { asm volatile("cp.async.commit_group;"); }
static __device__ __forceinline__ void cp_wait0()  { asm volatile("cp.async.wait_group 0;"); }

struct Coef {
    u64 cl0, cl1, cl2, cl3;   // lo: (R0,R1)(R2,R3)(R4,R5)(R6,R7)
    u64 ch0, ch1, ch2, ch3;   // hi: H_t = (-1)^t R_{7-t}
};
static __device__ __forceinline__ Coef make_coef() {
    Coef c;
    c.cl0 = pack2(R0, R1);  c.cl1 = pack2(R2, R3);
    c.cl2 = pack2(R4, R5);  c.cl3 = pack2(R6, R7);
    c.ch0 = pack2(R7, -R6); c.ch1 = pack2(R5, -R4);
    c.ch2 = pack2(R3, -R2); c.ch3 = pack2(R1, -R0);
    return c;
}

// Prefetch a row into A (cp.async) and fill A's halo straight from GMEM.
static __device__ __forceinline__ void prefetch_row(float* Aext, const float* xr) {
    #pragma unroll
    for (int k = 0; k < L0 / 4 / NT; k++) {
        int i = threadIdx.x + k * NT;
        cp16(Aext + 8 + 4 * i, xr + 4 * i);
    }
    cp_commit();
    int t = threadIdx.x;
    if (t < 6) {
        Aext[2 + t] = xr[5 - t];                 // in[-6..-1] = x[5..0]
    } else if (t < 13) {
        int m = t - 6;
        Aext[8 + L0 + m] = xr[L0 - 1 - m];       // in[n..n+6] = x[n-1..n-7]
    }
}

// One DWT level. p_k = (ext[2k], ext[2k+1]); output i uses p_{i+1}..p_{i+4}.
// Thread t owns outputs [t*T, t*T+T) in chunks of <=CH with batched preloads.
// RTHR >= 0: halo filled in-warp (left: threads 0..5 = warp 0 = left consumers;
// right: threads RTHR..RTHR+6, same warp as all right-halo consumers).
#define CH 9
template<int T, int RTHR>
static __device__ __forceinline__ void dwt_level(
    float* __restrict__ ext, int n, int n_out,
    float* __restrict__ outA, float* __restrict__ outD)
{
    if (RTHR >= 0) {
        int t = threadIdx.x;
        if (t < 6) ext[2 + t] = ext[8 + 5 - t];                  // left halo
        if ((unsigned)(t - RTHR) < 7u) {
            int m = t - RTHR;
            ext[8 + n + m] = ext[8 + n - 1 - m];                 // right halo
        }
        __syncwarp();
    }
    const int i0 = threadIdx.x * T;
    if (i0 >= n_out) return;
    const int rem = n_out - i0;
    const int lim = rem < T ? rem : T;

    const Coef c = make_coef();
    const u64* pp = reinterpret_cast<const u64*>(ext) + (i0 + 1);

    #pragma unroll
    for (int base = 0; base < T; base += CH) {
        if (base < lim) {
            const int Bn = (lim - base < CH) ? (lim - base) : CH;
            u64 p[CH + 3];
            #pragma unroll
            for (int k = 0; k < CH + 3; k++)
                if (k < Bn + 3) p[k] = pp[base + k];
            #pragma unroll
            for (int j = 0; j < CH; j++) {
                if (j < T - base && j < Bn) {
                    u64 al = mul2(c.cl0, p[j]);
                    al = fma2(c.cl1, p[j + 1], al);
                    al = fma2(c.cl2, p[j + 2], al);
                    al = fma2(c.cl3, p[j + 3], al);
                    u64 ah = mul2(c.ch0, p[j]);
                    ah = fma2(c.ch1, p[j + 1], ah);
                    ah = fma2(c.ch2, p[j + 2], ah);
                    ah = fma2(c.ch3, p[j + 3], ah);
                    outA[i0 + base + j] = hadd2(al);
                    outD[i0 + base + j] = hadd2(ah);
                }
            }
        }
    }
}

// Coalesced u64 copy of n elements SMEM->GMEM; both bases must be 8B-aligned.
static __device__ __forceinline__ void copy_out_u64(
    const float* __restrict__ src, float* __restrict__ dst, int n)
{
    const u64* sp = reinterpret_cast<const u64*>(src);
    u64* gp = reinterpret_cast<u64*>(dst);
    #pragma unroll 4
    for (int p = threadIdx.x; p < n / 2; p += NT) gp[p] = sp[p];
    if ((n & 1) && threadIdx.x == 0) dst[n - 1] = src[n - 1];
}

__global__ void __launch_bounds__(NT, 3)
wavedec_db4_l4_kernel(const float* __restrict__ x, float* __restrict__ out)
{
    extern __shared__ float sm[];
    float* A = sm;                          // row (ext)
    float* B = A + CAP_A;                   // cA1, later cA3 (ext)
    float* C = B + CAP_B;                   // cA2 (ext)
    float* S = C + CAP_C;                   // cD staging (even base)

    prefetch_row(A, x + (size_t)blockIdx.x * L0);

    for (int r = blockIdx.x; r < NROWS; r += GRID) {
        float* orow = out + (size_t)r * TOT;

        cp_wait0();
        __syncthreads();                                  // P1: A ready (incl halo)

        // P2 — Level 1: 8192 -> 4099. cA1 -> B, cD1 -> S+1.
        dwt_level<17, -1>(A, L0, O1, B + 8, S + 1);
        __syncthreads();

        // P3 — prefetch next row | copy cD1 out (head odd -> scalar, rest u64).
        {
            int rn = r + GRID;
            if (rn < NROWS) prefetch_row(A, x + (size_t)rn * L0);
        }
        if (threadIdx.x == 0) orow[4119] = S[1];
        copy_out_u64(S + 2, orow + 4120, O1 - 1);         // 4098 elems, even both
        __syncthreads();                                  // S free

        // P4 — Level 2: 4099 -> 2053. cA2 -> C, cD2 -> S[0..2052].
        dwt_level<9, 224>(B, O1, O2, C + 8, S);
        __syncthreads();

        // P5 — Level 3 (reads C, writes B + S[2054..]) | copy cD2 (reads S[0..2052]).
        dwt_level<5, 192>(C, O2, O3, B + 8, S + 2054);
        copy_out_u64(S, orow + (O4 + O4 + O3), O2);       // base 2066 even
        __syncthreads();

        // P6 — Level 4 (reads B, writes GMEM direct) | copy cD3 (reads S[2054..]).
        dwt_level<3, 160>(B, O3, O4, orow, orow + O4);
        copy_out_u64(S + 2054, orow + (O4 + O4), O3);     // base 1036 even, 515 pairs
        __syncthreads();
    }
}

extern "C" void kernel_launch(void* const* d_in, const int* in_sizes, int n_in,
                              void* d_out, int out_size)
{
    (void)in_sizes; (void)n_in; (void)out_size;
    const float* x = (const float*)d_in[0];
    float* out = (float*)d_out;

    cudaFuncSetAttribute(wavedec_db4_l4_kernel,
                         cudaFuncAttributeMaxDynamicSharedMemorySize, SMEM_BYTES);
    wavedec_db4_l4_kernel<<<GRID, NT, SMEM_BYTES>>>(x, out);
}